// round 3
// baseline (speedup 1.0000x reference)
#include <cuda_runtime.h>

// QuarticBSplinePotential.
// f(x) = sum_j w_j * B4((x - c_j)/SCALE) is itself a uniform quartic spline in
// u = (x+3)/SCALE:  with s = u + 2.5, k = floor(s), g = s - k in [0,1), we have
//   f = (1/24) * [ P[k][0] + g*(P[k][1] + g*(P[k][2] + g*(P[k][3] + g*P[k][4]))) ]
// where P[k][p] = sum_m w[k-m] * C[m][p] and C are the fixed quartic B-spline
// basis-polynomial coefficients (x24):
//   C0=[0,0,0,0,1] C1=[1,4,6,4,-4] C2=[11,12,-6,-12,6] C3=[11,-12,-6,12,-4] C4=[1,-4,6,-4,1]
// P is precomputed per block (43 intervals: clamped k in [-5,37]); out-of-range
// weights are zero.

#define NTHREADS 256
#define NROWS    43        // k in [-5, 37] -> row = k + 5

__device__ float        g_accum = 0.0f;
__device__ unsigned int g_count = 0;

__device__ __forceinline__ float eval_elem(float xv, const float (*P)[8])
{
    float s  = fmaf(xv, 5.33333333333333333f, 18.5f);   // (x+3)*16/3 + 2.5
    int   ki = __float2int_rd(s);
    float g  = s - (float)ki;
    int   row = min(max(ki, -5), 37) + 5;

    float4 c = *(const float4*)&P[row][0];
    float  c4 = P[row][4];
    float h = fmaf(g, c4, c.w);
    h = fmaf(g, h, c.z);
    h = fmaf(g, h, c.y);
    return fmaf(g, h, c.x);          // x24
}

__global__ void __launch_bounds__(NTHREADS)
spline_sum_kernel(const float* __restrict__ x,
                  const float* __restrict__ weights,
                  float* __restrict__ out, int n, int nblocks)
{
    __shared__ float P[NROWS][8];    // rows padded to 32B for LDS.128
    __shared__ float wsum[NTHREADS / 32];

    const int tid = threadIdx.x;

    // Precompute per-interval quartic coefficients (one thread per row).
    if (tid < NROWS) {
        int k = tid - 5;
        float w0 = (k     >= 0 && k     <= 32) ? weights[k]     : 0.0f;
        float w1 = (k - 1 >= 0 && k - 1 <= 32) ? weights[k - 1] : 0.0f;
        float w2 = (k - 2 >= 0 && k - 2 <= 32) ? weights[k - 2] : 0.0f;
        float w3 = (k - 3 >= 0 && k - 3 <= 32) ? weights[k - 3] : 0.0f;
        float w4 = (k - 4 >= 0 && k - 4 <= 32) ? weights[k - 4] : 0.0f;
        P[tid][0] =        w1 + 11.0f*w2 + 11.0f*w3 +       w4;
        P[tid][1] =  4.0f*w1 + 12.0f*w2 - 12.0f*w3 - 4.0f*w4;
        P[tid][2] =  6.0f*w1 -  6.0f*w2 -  6.0f*w3 + 6.0f*w4;
        P[tid][3] =  4.0f*w1 - 12.0f*w2 + 12.0f*w3 - 4.0f*w4;
        P[tid][4] = w0 - 4.0f*w1 + 6.0f*w2 - 4.0f*w3 + w4;
        P[tid][5] = 0.0f; P[tid][6] = 0.0f; P[tid][7] = 0.0f;
    }
    __syncthreads();

    const int n4 = n >> 2;
    const float4* x4 = (const float4*)x;
    const int gsz = nblocks * NTHREADS;

    // Two independent float4 loads issued up front (MLP=2).
    int i0 = blockIdx.x * NTHREADS + tid;
    int i1 = i0 + gsz;
    float4 v0, v1;
    bool p0 = (i0 < n4), p1 = (i1 < n4);
    if (p0) v0 = x4[i0];
    if (p1) v1 = x4[i1];

    float acc = 0.0f;
    if (p0) {
        acc += eval_elem(v0.x, P); acc += eval_elem(v0.y, P);
        acc += eval_elem(v0.z, P); acc += eval_elem(v0.w, P);
    }
    if (p1) {
        acc += eval_elem(v1.x, P); acc += eval_elem(v1.y, P);
        acc += eval_elem(v1.z, P); acc += eval_elem(v1.w, P);
    }
    if (blockIdx.x == 0 && tid == 0) {          // scalar tail (n % 4)
        for (int t = n4 << 2; t < n; t++)
            acc += eval_elem(x[t], P);
    }

    // warp + block reduce
    #pragma unroll
    for (int o = 16; o > 0; o >>= 1)
        acc += __shfl_xor_sync(0xFFFFFFFFu, acc, o);
    int lane = tid & 31, wid = tid >> 5;
    if (lane == 0) wsum[wid] = acc;
    __syncthreads();

    if (tid == 0) {
        float p = 0.0f;
        #pragma unroll
        for (int w = 0; w < NTHREADS / 32; w++) p += wsum[w];
        atomicAdd(&g_accum, p);
        __threadfence();
        unsigned int ticket = atomicAdd(&g_count, 1u);
        if (ticket == (unsigned int)(nblocks - 1)) {
            __threadfence();
            float tot = *(volatile float*)&g_accum;
            out[0] = tot * (1.0f / 24.0f);
            *(volatile float*)&g_accum = 0.0f;   // reset for next replay
            *(volatile unsigned int*)&g_count = 0u;
            __threadfence();
        }
    }
}

extern "C" void kernel_launch(void* const* d_in, const int* in_sizes, int n_in,
                              void* d_out, int out_size)
{
    const float* x = (const float*)d_in[0];
    const float* w = (const float*)d_in[1];
    int n = in_sizes[0];
    if (n_in >= 2 && in_sizes[0] == 33 && in_sizes[1] > 33) {   // order robustness
        x = (const float*)d_in[1];
        w = (const float*)d_in[0];
        n = in_sizes[1];
    }
    int n4 = n >> 2;
    int nblocks = (n4 + 2 * NTHREADS - 1) / (2 * NTHREADS);     // 2 float4/thread
    if (nblocks < 1) nblocks = 1;
    spline_sum_kernel<<<nblocks, NTHREADS>>>(x, w, (float*)d_out, n, nblocks);
}